// round 5
// baseline (speedup 1.0000x reference)
#include <cuda_runtime.h>
#include <math.h>

#define BB 32
#define PP 24
#define SS 48
#define HH 512
#define FF 64
#define DD 576      // H + F
#define G4 2048     // 4*H
#define OO 16
#define NBLK_RECUR 128

// ---------------- device scratch (no runtime allocation) ----------------
__device__ float g_seq[PP*BB*DD];                 // [t][b][d]
__device__ float g_xrev[BB*DD];                   // [b][d] = seq[lens[b]-1][b][:]
__device__ float g_preact[PP*G4*BB];              // [t][g][b]
__device__ float g_preB[G4*BB];                   // [g][b]   backward-step gates
__device__ unsigned long long g_hU[2][HH*BB/2];   // pair-packed h: float view [(j>>1)*64 + b*2 + (j&1)]
__device__ float g_hb[BB*HH];                     // backward h [b][j]
__device__ int g_mask_u8;
__device__ unsigned g_cnt = 0;
__device__ unsigned g_gen = 0;

// ---------------- helpers ----------------
__device__ __forceinline__ unsigned long long ffma2(unsigned long long a, unsigned long long b, unsigned long long c){
    unsigned long long d;
    asm("fma.rn.f32x2 %0, %1, %2, %3;" : "=l"(d) : "l"(a), "l"(b), "l"(c));
    return d;
}
__device__ __forceinline__ float2 u2f(unsigned long long v){
    float2 r; asm("mov.b64 {%0,%1}, %2;" : "=f"(r.x), "=f"(r.y) : "l"(v)); return r;
}
__device__ __forceinline__ float sigf(float x){ return 1.0f/(1.0f + __expf(-x)); }
__device__ __forceinline__ float tanhfast(float x){ return 1.0f - 2.0f/(__expf(2.0f*x) + 1.0f); }

__device__ __forceinline__ void gridbar(int nb){
    __syncthreads();
    if (threadIdx.x == 0){
        volatile unsigned* genp = &g_gen;
        unsigned my = *genp;
        __threadfence();
        if (atomicAdd(&g_cnt, 1u) == (unsigned)(nb-1)){
            g_cnt = 0u;
            __threadfence();
            *genp = my + 1u;
        } else {
            while (*genp == my) { }
        }
    }
    __syncthreads();
}

// ---------------- probe: is x_mask stored as u8 or int32? ----------------
// Read only N/4 int32 = N bytes (safe under either storage). If u8-packed,
// monotone 0..0 1..1 rows produce words like 0x01010101 (>1). If int32, all 0/1.
__global__ void probe_kernel(const unsigned* __restrict__ xm){
    __shared__ int found;
    if (threadIdx.x == 0) found = 0;
    __syncthreads();
    const int n4 = (BB*PP*SS)/4;
    for (int i = threadIdx.x; i < n4; i += 256){
        if (xm[i] > 1u) found = 1;
    }
    __syncthreads();
    if (threadIdx.x == 0) g_mask_u8 = found;
}

__global__ void init_kernel(){
    int i = blockIdx.x*256 + threadIdx.x;
    if (i < HH*BB/2) g_hU[0][i] = 0ull;
}

// ---------------- attention pooling: one block per (b,p) ----------------
__global__ void __launch_bounds__(256) attn_kernel(const int* __restrict__ x,
        const void* __restrict__ xmask, const float* __restrict__ xfeat,
        const float* __restrict__ emb, const float* __restrict__ wattn,
        const float* __restrict__ battn)
{
    int bp = blockIdx.x; int b = bp / PP, p = bp % PP;
    __shared__ float sw[HH];
    __shared__ float ssc[SS];
    __shared__ float sal[SS];
    __shared__ int sidx[SS];
    __shared__ int smk[SS];
    int tid = threadIdx.x, lane = tid & 31, w = tid >> 5;
    int msku8 = g_mask_u8;

    for (int i = tid; i < HH; i += 256) sw[i] = wattn[i];
    __syncthreads();

    // pass 1: attention scores (one warp per sentence position)
    for (int s = w; s < SS; s += 8){
        long off = (long)(b*PP + p)*SS + s;
        int idx = 0, mk = 0;
        if (lane == 0){
            idx = x[off];
            mk  = msku8 ? (int)((const unsigned char*)xmask)[off]
                        : (((const int*)xmask)[off] != 0);
        }
        idx = __shfl_sync(0xffffffffu, idx, 0);
        const float* er = emb + (long)idx*HH;
        float acc = 0.f;
        #pragma unroll 4
        for (int i = lane; i < HH; i += 32) acc += er[i]*sw[i];
        #pragma unroll
        for (int o = 16; o; o >>= 1) acc += __shfl_xor_sync(0xffffffffu, acc, o);
        if (lane == 0){ sidx[s]=idx; smk[s]=mk; ssc[s] = mk ? -1e30f : (acc + battn[0]); }
    }
    __syncthreads();

    if (tid == 0){
        float m = -3.4e38f;
        for (int s = 0; s < SS; s++) m = fmaxf(m, ssc[s]);
        float sum = 0.f;
        for (int s = 0; s < SS; s++){ float e = __expf(ssc[s]-m); sal[s]=e; sum += e; }
        float inv = 1.f/sum;
        for (int s = 0; s < SS; s++) sal[s] = smk[s] ? 0.f : sal[s]*inv;
    }
    __syncthreads();

    // pass 2: weighted pooling -> seq[t=p][b][d]
    float* outrow = g_seq + (long)(p*BB + b)*DD;
    for (int d = tid; d < DD; d += 256){
        float acc = 0.f;
        if (d < HH){
            for (int s = 0; s < SS; s++){
                float a = sal[s];
                if (a != 0.f) acc += a * emb[(long)sidx[s]*HH + d];
            }
        } else {
            int f = d - HH;
            const float* xf = xfeat + ((long)(b*PP+p)*SS)*FF + f;
            for (int s = 0; s < SS; s++) if (!smk[s]) acc += xf[s*FF];
        }
        outrow[d] = acc;
    }
}

// ---------------- gather seq[lens[b]-1][b] for the single backward step ----------------
__global__ void xrev_kernel(const int* __restrict__ lens){
    int i = blockIdx.x*256 + threadIdx.x;
    if (i < BB*DD){
        int b = i/DD, d = i - b*DD;
        int t = lens[b]-1;
        g_xrev[i] = g_seq[((long)t*BB+b)*DD + d];
    }
}

// ---------------- pre-GEMM: [800,576]@[576,2048]^T + bias, ffma2 with a-dup ----------------
__global__ void __launch_bounds__(256) pregemm_kernel(
    const float* __restrict__ Wf, const float* __restrict__ bif, const float* __restrict__ bhf,
    const float* __restrict__ Wb, const float* __restrict__ bib, const float* __restrict__ bhb)
{
    __shared__ float As2[16][128];  // A tile, each value duplicated (for packed ffma2)
    __shared__ float Bs[16][64];
    int mx = blockIdx.x, nx = blockIdx.y;
    const float* A; const float* Wih; const float* b1; const float* b2;
    int Mloc, row0;
    if (mx < 12){ A = g_seq;  row0 = mx*64; Mloc = 64; Wih = Wf; b1 = bif; b2 = bhf; }
    else        { A = g_xrev; row0 = 0;     Mloc = 32; Wih = Wb; b1 = bib; b2 = bhb; }
    int n0blk = nx*64;
    int tid = threadIdx.x;
    int tx = tid & 15, ty = tid >> 4;

    unsigned long long acc[4][2];
    #pragma unroll
    for (int i = 0; i < 4; i++){ acc[i][0] = 0ull; acc[i][1] = 0ull; }

    int lr = tid >> 2;
    int lk = (tid & 3) * 4;

    for (int k0 = 0; k0 < DD; k0 += 16){
        float4 av = make_float4(0.f,0.f,0.f,0.f);
        if (lr < Mloc) av = *(const float4*)(A + (long)(row0+lr)*DD + k0 + lk);
        float4 bv = *(const float4*)(Wih + (long)(n0blk+lr)*DD + k0 + lk);
        __syncthreads();
        As2[lk+0][2*lr] = av.x; As2[lk+0][2*lr+1] = av.x;
        As2[lk+1][2*lr] = av.y; As2[lk+1][2*lr+1] = av.y;
        As2[lk+2][2*lr] = av.z; As2[lk+2][2*lr+1] = av.z;
        As2[lk+3][2*lr] = av.w; As2[lk+3][2*lr+1] = av.w;
        Bs[lk+0][lr] = bv.x; Bs[lk+1][lr] = bv.y; Bs[lk+2][lr] = bv.z; Bs[lk+3][lr] = bv.w;
        __syncthreads();
        #pragma unroll
        for (int k = 0; k < 16; k++){
            const unsigned long long* ap = (const unsigned long long*)&As2[k][ty*8];
            const unsigned long long* bp = (const unsigned long long*)&Bs[k][tx*4];
            unsigned long long b01 = bp[0], b23 = bp[1];
            unsigned long long a0 = ap[0], a1 = ap[1], a2 = ap[2], a3 = ap[3];
            acc[0][0]=ffma2(a0,b01,acc[0][0]); acc[0][1]=ffma2(a0,b23,acc[0][1]);
            acc[1][0]=ffma2(a1,b01,acc[1][0]); acc[1][1]=ffma2(a1,b23,acc[1][1]);
            acc[2][0]=ffma2(a2,b01,acc[2][0]); acc[2][1]=ffma2(a2,b23,acc[2][1]);
            acc[3][0]=ffma2(a3,b01,acc[3][0]); acc[3][1]=ffma2(a3,b23,acc[3][1]);
        }
    }

    int n0 = n0blk + tx*4;
    float bias[4];
    #pragma unroll
    for (int j = 0; j < 4; j++) bias[j] = b1[n0+j] + b2[n0+j];
    #pragma unroll
    for (int ii = 0; ii < 4; ii++){
        int i = ty*4 + ii;
        if (i < Mloc){
            int m = row0 + i;
            float2 c01 = u2f(acc[ii][0]); float2 c23 = u2f(acc[ii][1]);
            float v0 = c01.x+bias[0], v1 = c01.y+bias[1], v2 = c23.x+bias[2], v3 = c23.y+bias[3];
            if (mx < 12){
                int t = m >> 5, b = m & 31;
                long base = ((long)t*G4 + n0)*BB + b;
                g_preact[base      ] = v0;
                g_preact[base+BB   ] = v1;
                g_preact[base+2*BB ] = v2;
                g_preact[base+3*BB ] = v3;
            } else {
                int b = m;
                g_preB[(n0+0)*BB + b] = v0;
                g_preB[(n0+1)*BB + b] = v1;
                g_preB[(n0+2)*BB + b] = v2;
                g_preB[(n0+3)*BB + b] = v3;
            }
        }
    }
}

// ---------------- persistent forward recurrence: 24 steps, grid barrier per step ----------------
// 128 blocks, block bk owns j in [bk*4, bk*4+4) and all 4 gates of those j.
// Warp w reduces k-slice [w*64, w*64+64); partials combined via smem; c stays in regs.
__global__ void __launch_bounds__(256) recur_kernel(const float* __restrict__ Whh){
    __shared__ float Ws[16*512];        // 32 KB: Whh rows for this block's 16 gates
    __shared__ float part_s[8*16*32];   // 16 KB: [warp][gate_local][b]
    int tid = threadIdx.x;
    int bk = blockIdx.x;
    int j0 = bk*4;

    for (int i = tid; i < 16*512; i += 256){
        int gl = i >> 9, k = i & 511;
        int q = gl >> 2, jj = gl & 3;
        Ws[i] = Whh[((long)(q*HH + j0 + jj))*HH + k];
    }
    __syncthreads();

    int lane = tid & 31, w = tid >> 5;
    int rb = lane, rjj = w & 3;   // reduction role (tid<128): b=tid%32, jj=tid/32
    float c_reg = 0.f;
    int pbase = w*32;             // this warp's k-pair slice

    for (int t = 0; t < PP; t++){
        const unsigned long long* cur = g_hU[t & 1];
        unsigned long long acc[16];
        #pragma unroll
        for (int i = 0; i < 16; i++) acc[i] = 0ull;

        #pragma unroll 4
        for (int pp = 0; pp < 32; pp += 2){
            unsigned long long h0 = __ldcg(cur + (pbase+pp  )*32 + lane);
            unsigned long long h1 = __ldcg(cur + (pbase+pp+1)*32 + lane);
            #pragma unroll
            for (int gl = 0; gl < 16; gl++){
                ulonglong2 wv = *(const ulonglong2*)(Ws + gl*512 + (pbase+pp)*2);
                acc[gl] = ffma2(h0, wv.x, acc[gl]);
                acc[gl] = ffma2(h1, wv.y, acc[gl]);
            }
        }
        #pragma unroll
        for (int gl = 0; gl < 16; gl++){
            float2 f = u2f(acc[gl]);
            part_s[(w*16+gl)*32 + lane] = f.x + f.y;
        }
        __syncthreads();

        if (tid < 128){
            float val[4];
            #pragma unroll
            for (int q = 0; q < 4; q++){
                int gl = q*4 + rjj;
                float v = g_preact[((long)t*G4 + q*HH + j0 + rjj)*BB + rb];
                #pragma unroll
                for (int ww = 0; ww < 8; ww++) v += part_s[(ww*16+gl)*32 + rb];
                val[q] = v;
            }
            c_reg = sigf(val[1])*c_reg + sigf(val[0])*tanhfast(val[2]);
            float h = sigf(val[3])*tanhfast(c_reg);
            int j = j0 + rjj;
            ((float*)g_hU[(t+1)&1])[(j>>1)*64 + rb*2 + (j&1)] = h;
        }
        gridbar(NBLK_RECUR);
    }
}

// ---------------- backward LSTM: single step from zero state = pointwise on preB ----------------
__global__ void bwd_kernel(){
    int id = blockIdx.x*256 + threadIdx.x;
    if (id < BB*HH){
        int j = id >> 5, b = id & 31;
        float ii = g_preB[(0*HH+j)*BB + b];
        float gg = g_preB[(2*HH+j)*BB + b];
        float oo = g_preB[(3*HH+j)*BB + b];
        float c = sigf(ii)*tanhfast(gg);      // sig(f)*c0 = 0
        g_hb[b*HH + j] = sigf(oo)*tanhfast(c);
    }
}

// ---------------- epilogue: reshape-scramble FC + layernorm + relu + log_softmax(axis=0) ----------------
// y[i,o] = bfc[o] + sum_{q,r} last[r, i*32+q] * Wfc[o, q*32+r];  last masked by lens[r]==24
__global__ void __launch_bounds__(256) epi_kernel(const int* __restrict__ lens,
    const float* __restrict__ Wfc, const float* __restrict__ bfc,
    const float* __restrict__ gamma, const float* __restrict__ beta,
    float* __restrict__ out)
{
    int o = blockIdx.x;
    __shared__ float part2[8][32];
    __shared__ int vmask[32];
    int tid = threadIdx.x;
    if (tid < 32) vmask[tid] = (lens[tid] > 23) ? 1 : 0;
    __syncthreads();

    int i = tid & 31, pp = tid >> 5;
    const float* hf = (const float*)g_hU[0];   // final forward h (after 24 steps)
    float acc = 0.f;
    #pragma unroll
    for (int qq = 0; qq < 4; qq++){
        int q = pp*4 + qq;
        int m = i*32 + q;
        const float* wrow = Wfc + (long)o*1024 + q*32;
        if (m < 512){
            int base = (m>>1)*64 + (m&1);
            #pragma unroll 8
            for (int r = 0; r < 32; r++)
                if (vmask[r]) acc += hf[base + r*2] * wrow[r];
        } else {
            int mm = m - 512;
            #pragma unroll 8
            for (int r = 0; r < 32; r++)
                if (vmask[r]) acc += g_hb[r*HH + mm] * wrow[r];
        }
    }
    part2[pp][i] = acc;
    __syncthreads();

    if (tid < 32){
        float y = bfc[o];
        #pragma unroll
        for (int p2 = 0; p2 < 8; p2++) y += part2[p2][tid];
        float s = y, s2 = y*y;
        #pragma unroll
        for (int off = 16; off; off >>= 1){
            s  += __shfl_xor_sync(0xffffffffu, s,  off);
            s2 += __shfl_xor_sync(0xffffffffu, s2, off);
        }
        float mean = s * (1.f/32.f);
        float var  = s2 * (1.f/32.f) - mean*mean;
        float yn = gamma[o]*(y-mean)*rsqrtf(var + 1e-5f) + beta[o];
        yn = fmaxf(yn, 0.f);
        float mx = yn;
        #pragma unroll
        for (int off = 16; off; off >>= 1) mx = fmaxf(mx, __shfl_xor_sync(0xffffffffu, mx, off));
        float e = __expf(yn - mx), se = e;
        #pragma unroll
        for (int off = 16; off; off >>= 1) se += __shfl_xor_sync(0xffffffffu, se, off);
        out[tid*OO + o] = yn - mx - __logf(se);
    }
}

// ---------------- launcher ----------------
extern "C" void kernel_launch(void* const* d_in, const int* in_sizes, int n_in,
                              void* d_out, int out_size)
{
    const int*  x     = (const int*)d_in[0];
    const void* xmask = d_in[1];
    const float* xfeat = (const float*)d_in[2];
    const int*  lens  = (const int*)d_in[3];

    // clause/cls scalars at 4,5 — self-correct if the harness dropped them
    int base = 6;
    if (n_in < 21 || in_sizes[6] != 50000*512) base = 4;

    const float* emb   = (const float*)d_in[base+0];
    const float* wattn = (const float*)d_in[base+1];
    const float* battn = (const float*)d_in[base+2];
    const float* Wih_f = (const float*)d_in[base+3];
    const float* Whh_f = (const float*)d_in[base+4];
    const float* bih_f = (const float*)d_in[base+5];
    const float* bhh_f = (const float*)d_in[base+6];
    const float* Wih_b = (const float*)d_in[base+7];
    const float* bih_b = (const float*)d_in[base+9];
    const float* bhh_b = (const float*)d_in[base+10];
    const float* Wfc   = (const float*)d_in[base+11];
    const float* bfc   = (const float*)d_in[base+12];
    const float* gamma = (const float*)d_in[base+13];
    const float* beta  = (const float*)d_in[base+14];
    float* out = (float*)d_out;
    (void)in_sizes; (void)out_size;

    probe_kernel<<<1,256>>>((const unsigned*)xmask);
    init_kernel<<<32,256>>>();
    attn_kernel<<<BB*PP,256>>>(x, xmask, xfeat, emb, wattn, battn);
    xrev_kernel<<<72,256>>>(lens);
    pregemm_kernel<<<dim3(13,32),256>>>(Wih_f, bih_f, bhh_f, Wih_b, bih_b, bhh_b);
    recur_kernel<<<NBLK_RECUR,256>>>(Whh_f);
    bwd_kernel<<<64,256>>>();
    epi_kernel<<<OO,256>>>(lens, Wfc, bfc, gamma, beta, out);
}

// round 9
// speedup vs baseline: 1.5618x; 1.5618x over previous
#include <cuda_runtime.h>
#include <math.h>

#define BB 32
#define PP 24
#define SS 48
#define HH 512
#define FF 64
#define DD 576      // H + F
#define G4 2048     // 4*H
#define OO 16
#define NBLK_RECUR 128

// ---------------- device scratch (no runtime allocation) ----------------
__device__ float g_seq[PP*BB*DD];     // [t][b][d]
__device__ float g_preact[PP*G4*BB];  // [t][g][b]
__device__ float g_preB[G4*BB];       // [g][b]   backward-step gates
__device__ float g_h[2][BB*HH];       // h double buffer, [b][k]
__device__ float g_hb[BB*HH];         // backward h [b][j]
__device__ int g_mask_u8;
__device__ int g_nb;                  // #batches with lens==24 (prefix, since sorted desc)
__device__ unsigned g_cnt = 0;
__device__ unsigned g_gen = 0;

// ---------------- helpers ----------------
__device__ __forceinline__ unsigned long long ffma2(unsigned long long a, unsigned long long b, unsigned long long c){
    unsigned long long d;
    asm("fma.rn.f32x2 %0, %1, %2, %3;" : "=l"(d) : "l"(a), "l"(b), "l"(c));
    return d;
}
__device__ __forceinline__ float2 u2f(unsigned long long v){
    float2 r; asm("mov.b64 {%0,%1}, %2;" : "=f"(r.x), "=f"(r.y) : "l"(v)); return r;
}
__device__ __forceinline__ float sigf(float x){ return 1.0f/(1.0f + __expf(-x)); }
__device__ __forceinline__ float tanhfast(float x){ return 1.0f - 2.0f/(__expf(2.0f*x) + 1.0f); }

__device__ __forceinline__ void gridbar(int nb){
    __syncthreads();
    if (threadIdx.x == 0){
        volatile unsigned* genp = &g_gen;
        unsigned my = *genp;
        __threadfence();
        if (atomicAdd(&g_cnt, 1u) == (unsigned)(nb-1)){
            g_cnt = 0u;
            __threadfence();
            *genp = my + 1u;
        } else {
            while (*genp == my) { }
        }
    }
    __syncthreads();
}

// ---------------- init: probe mask dtype, count valid batches, zero h0 ----------------
// probe reads only N/4 int32 = N bytes (safe under u8 or int32 storage).
__global__ void init_kernel(const unsigned* __restrict__ xm, const int* __restrict__ lens){
    int bid = blockIdx.x, tid = threadIdx.x;
    if (bid == 0){
        __shared__ int found;
        if (tid == 0) found = 0;
        __syncthreads();
        const int n4 = (BB*PP*SS)/4;
        for (int i = tid; i < n4; i += 256) if (xm[i] > 1u) found = 1;
        __syncthreads();
        if (tid == 0) g_mask_u8 = found;
    } else if (bid == 1){
        if (tid == 0){
            int c = 0;
            for (int i = 0; i < BB; i++) c += (lens[i] > 23) ? 1 : 0;
            g_nb = c;
        }
    } else {
        int i = (bid-2)*256 + tid;
        if (i < BB*HH) g_h[0][i] = 0.f;
    }
}

// ---------------- attention pooling: one block per (b,p); only valid b do work ----------------
__global__ void __launch_bounds__(256) attn_kernel(const int* __restrict__ x,
        const void* __restrict__ xmask, const float* __restrict__ xfeat,
        const float* __restrict__ emb, const float* __restrict__ wattn,
        const float* __restrict__ battn, const int* __restrict__ lens)
{
    int bp = blockIdx.x; int b = bp / PP, p = bp % PP;
    if (lens[b] < 24) return;            // only lens==24 batches reach the output
    __shared__ float sw[HH];
    __shared__ float ssc[SS];
    __shared__ float sal[SS];
    __shared__ int sidx[SS];
    __shared__ int smk[SS];
    int tid = threadIdx.x, lane = tid & 31, w = tid >> 5;
    int msku8 = g_mask_u8;

    for (int i = tid; i < HH; i += 256) sw[i] = wattn[i];
    __syncthreads();

    // pass 1: attention scores (one warp per sentence position)
    for (int s = w; s < SS; s += 8){
        long off = (long)(b*PP + p)*SS + s;
        int idx = 0, mk = 0;
        if (lane == 0){
            idx = x[off];
            mk  = msku8 ? (int)((const unsigned char*)xmask)[off]
                        : (((const int*)xmask)[off] != 0);
        }
        idx = __shfl_sync(0xffffffffu, idx, 0);
        const float* er = emb + (long)idx*HH;
        float acc = 0.f;
        #pragma unroll 4
        for (int i = lane; i < HH; i += 32) acc += er[i]*sw[i];
        #pragma unroll
        for (int o = 16; o; o >>= 1) acc += __shfl_xor_sync(0xffffffffu, acc, o);
        if (lane == 0){ sidx[s]=idx; smk[s]=mk; ssc[s] = mk ? -1e30f : (acc + battn[0]); }
    }
    __syncthreads();

    if (tid == 0){
        float m = -3.4e38f;
        for (int s = 0; s < SS; s++) m = fmaxf(m, ssc[s]);
        float sum = 0.f;
        for (int s = 0; s < SS; s++){ float e = __expf(ssc[s]-m); sal[s]=e; sum += e; }
        float inv = 1.f/sum;
        for (int s = 0; s < SS; s++) sal[s] = smk[s] ? 0.f : sal[s]*inv;
    }
    __syncthreads();

    // pass 2: weighted pooling -> seq[t=p][b][d]
    float* outrow = g_seq + (long)(p*BB + b)*DD;
    for (int d = tid; d < DD; d += 256){
        float acc = 0.f;
        if (d < HH){
            for (int s = 0; s < SS; s++){
                float a = sal[s];
                if (a != 0.f) acc += a * emb[(long)sidx[s]*HH + d];
            }
        } else {
            int f = d - HH;
            const float* xf = xfeat + ((long)(b*PP+p)*SS)*FF + f;
            for (int s = 0; s < SS; s++) if (!smk[s]) acc += xf[s*FF];
        }
        outrow[d] = acc;
    }
}

// ---------------- pre-GEMM over compacted valid rows ----------------
// forward rows m = t*nb + b (m < 24*nb), backward rows b < nb with A = seq[23][b]
__global__ void __launch_bounds__(256) pregemm_kernel(
    const float* __restrict__ Wf, const float* __restrict__ bif, const float* __restrict__ bhf,
    const float* __restrict__ Wb, const float* __restrict__ bib, const float* __restrict__ bhb)
{
    __shared__ float As2[16][128];  // A tile, each value duplicated (for packed ffma2)
    __shared__ float Bs[16][64];
    int nb = g_nb;
    int mx = blockIdx.x, nx = blockIdx.y;
    int fwd = (mx < 12);
    int row0 = fwd ? mx*64 : 0;
    if (fwd && row0 >= 24*nb) return;
    const float* Wih; const float* b1; const float* b2;
    if (fwd){ Wih = Wf; b1 = bif; b2 = bhf; }
    else    { Wih = Wb; b1 = bib; b2 = bhb; }
    int n0blk = nx*64;
    int tid = threadIdx.x;
    int tx = tid & 15, ty = tid >> 4;

    unsigned long long acc[4][2];
    #pragma unroll
    for (int i = 0; i < 4; i++){ acc[i][0] = 0ull; acc[i][1] = 0ull; }

    int lr = tid >> 2;
    int lk = (tid & 3) * 4;

    // hoist the A row pointer for this thread's load row
    const float* Arow = 0;
    if (fwd){
        int m = row0 + lr;
        if (m < 24*nb){ int t = m / nb, b = m - t*nb; Arow = g_seq + ((long)t*BB + b)*DD; }
    } else {
        if (lr < nb) Arow = g_seq + ((long)23*BB + lr)*DD;
    }

    for (int k0 = 0; k0 < DD; k0 += 16){
        float4 av = make_float4(0.f,0.f,0.f,0.f);
        if (Arow) av = *(const float4*)(Arow + k0 + lk);
        float4 bv = *(const float4*)(Wih + (long)(n0blk+lr)*DD + k0 + lk);
        __syncthreads();
        As2[lk+0][2*lr] = av.x; As2[lk+0][2*lr+1] = av.x;
        As2[lk+1][2*lr] = av.y; As2[lk+1][2*lr+1] = av.y;
        As2[lk+2][2*lr] = av.z; As2[lk+2][2*lr+1] = av.z;
        As2[lk+3][2*lr] = av.w; As2[lk+3][2*lr+1] = av.w;
        Bs[lk+0][lr] = bv.x; Bs[lk+1][lr] = bv.y; Bs[lk+2][lr] = bv.z; Bs[lk+3][lr] = bv.w;
        __syncthreads();
        #pragma unroll
        for (int k = 0; k < 16; k++){
            const unsigned long long* ap = (const unsigned long long*)&As2[k][ty*8];
            const unsigned long long* bp = (const unsigned long long*)&Bs[k][tx*4];
            unsigned long long b01 = bp[0], b23 = bp[1];
            unsigned long long a0 = ap[0], a1 = ap[1], a2 = ap[2], a3 = ap[3];
            acc[0][0]=ffma2(a0,b01,acc[0][0]); acc[0][1]=ffma2(a0,b23,acc[0][1]);
            acc[1][0]=ffma2(a1,b01,acc[1][0]); acc[1][1]=ffma2(a1,b23,acc[1][1]);
            acc[2][0]=ffma2(a2,b01,acc[2][0]); acc[2][1]=ffma2(a2,b23,acc[2][1]);
            acc[3][0]=ffma2(a3,b01,acc[3][0]); acc[3][1]=ffma2(a3,b23,acc[3][1]);
        }
    }

    int n0 = n0blk + tx*4;
    float bias[4];
    #pragma unroll
    for (int j = 0; j < 4; j++) bias[j] = b1[n0+j] + b2[n0+j];
    #pragma unroll
    for (int ii = 0; ii < 4; ii++){
        int i = ty*4 + ii;
        int m = row0 + i;
        float2 c01 = u2f(acc[ii][0]); float2 c23 = u2f(acc[ii][1]);
        float v0 = c01.x+bias[0], v1 = c01.y+bias[1], v2 = c23.x+bias[2], v3 = c23.y+bias[3];
        if (fwd){
            if (m < 24*nb){
                int t = m / nb, b = m - t*nb;
                long base = ((long)t*G4 + n0)*BB + b;
                g_preact[base      ] = v0;
                g_preact[base+BB   ] = v1;
                g_preact[base+2*BB ] = v2;
                g_preact[base+3*BB ] = v3;
            }
        } else {
            if (i < nb){
                g_preB[(n0+0)*BB + i] = v0;
                g_preB[(n0+1)*BB + i] = v1;
                g_preB[(n0+2)*BB + i] = v2;
                g_preB[(n0+3)*BB + i] = v3;
            }
        }
    }
}

// ---------------- persistent forward recurrence over nb valid columns ----------------
// 128 blocks; block bk owns 16 gate rows (4 j x 4 gate types). Whh tile in smem.
// Per step: warp-per-dot over 16*nb dots; preact prefetched; c in registers.
__global__ void __launch_bounds__(256) recur_kernel(const float* __restrict__ Whh){
    __shared__ float Ws[16*512];     // 32 KB
    __shared__ float sdot[16*32];
    int tid = threadIdx.x, lane = tid & 31, w = tid >> 5;
    int bk = blockIdx.x, j0 = bk*4;
    int nb = g_nb;

    for (int i = tid; i < 16*512; i += 256){
        int gl = i >> 9, k = i & 511;
        int q = gl >> 2, jj = gl & 3;
        Ws[i] = Whh[((long)(q*HH + j0 + jj))*HH + k];
    }
    __syncthreads();

    int gjj = tid >> 5, gb = tid & 31;
    bool gate_active = (tid < 128) && (gb < nb);
    float c_reg = 0.f;

    for (int t = 0; t < PP; t++){
        // prefetch gate preactivations (L2 latency hides behind the dot phase)
        float pre0=0.f, pre1=0.f, pre2=0.f, pre3=0.f;
        if (gate_active){
            long pb = ((long)t*G4 + j0 + gjj)*BB + gb;
            pre0 = g_preact[pb];
            pre1 = g_preact[pb + (long)HH*BB];
            pre2 = g_preact[pb + (long)2*HH*BB];
            pre3 = g_preact[pb + (long)3*HH*BB];
        }
        const float* hcur = g_h[t & 1];
        for (int idx = w; idx < 16*nb; idx += 8){
            int gl = idx & 15, b = idx >> 4;
            const float* hrow = hcur + b*HH;
            const float* wrow = Ws + gl*512;
            float a0=0.f,a1=0.f,a2=0.f,a3=0.f;
            #pragma unroll
            for (int kk = 0; kk < 16; kk += 4){
                a0 += wrow[(kk+0)*32+lane] * __ldcg(hrow + (kk+0)*32+lane);
                a1 += wrow[(kk+1)*32+lane] * __ldcg(hrow + (kk+1)*32+lane);
                a2 += wrow[(kk+2)*32+lane] * __ldcg(hrow + (kk+2)*32+lane);
                a3 += wrow[(kk+3)*32+lane] * __ldcg(hrow + (kk+3)*32+lane);
            }
            float acc = (a0+a1)+(a2+a3);
            #pragma unroll
            for (int o = 16; o; o >>= 1) acc += __shfl_xor_sync(0xffffffffu, acc, o);
            if (lane == 0) sdot[gl*32 + b] = acc;
        }
        __syncthreads();
        if (gate_active){
            float vi = pre0 + sdot[(0*4+gjj)*32 + gb];
            float vf = pre1 + sdot[(1*4+gjj)*32 + gb];
            float vg = pre2 + sdot[(2*4+gjj)*32 + gb];
            float vo = pre3 + sdot[(3*4+gjj)*32 + gb];
            c_reg = sigf(vf)*c_reg + sigf(vi)*tanhfast(vg);
            float h = sigf(vo)*tanhfast(c_reg);
            g_h[(t+1)&1][gb*HH + j0 + gjj] = h;
        }
        gridbar(NBLK_RECUR);
    }
}

// ---------------- backward LSTM: single step from zero state = pointwise on preB ----------------
__global__ void bwd_kernel(){
    int nb = g_nb;
    int id = blockIdx.x*256 + threadIdx.x;
    if (id < BB*HH){
        int j = id >> 5, b = id & 31;
        if (b >= nb) return;
        float ii = g_preB[(0*HH+j)*BB + b];
        float gg = g_preB[(2*HH+j)*BB + b];
        float oo = g_preB[(3*HH+j)*BB + b];
        float c = sigf(ii)*tanhfast(gg);      // sig(f)*c0 = 0
        g_hb[b*HH + j] = sigf(oo)*tanhfast(c);
    }
}

// ---------------- epilogue: reshape-scramble FC + layernorm + relu + log_softmax(axis=0) ----------------
__global__ void __launch_bounds__(256) epi_kernel(const int* __restrict__ lens,
    const float* __restrict__ Wfc, const float* __restrict__ bfc,
    const float* __restrict__ gamma, const float* __restrict__ beta,
    float* __restrict__ out)
{
    int o = blockIdx.x;
    __shared__ float part2[8][32];
    __shared__ int vmask[32];
    int tid = threadIdx.x;
    if (tid < 32) vmask[tid] = (lens[tid] > 23) ? 1 : 0;
    __syncthreads();

    int i = tid & 31, pp = tid >> 5;
    const float* hf = g_h[0];   // final forward h after 24 steps (even parity)
    float acc = 0.f;
    #pragma unroll
    for (int qq = 0; qq < 4; qq++){
        int q = pp*4 + qq;
        int m = i*32 + q;
        const float* wrow = Wfc + (long)o*1024 + q*32;
        if (m < 512){
            #pragma unroll 8
            for (int r = 0; r < 32; r++)
                if (vmask[r]) acc += hf[r*HH + m] * wrow[r];
        } else {
            int mm = m - 512;
            #pragma unroll 8
            for (int r = 0; r < 32; r++)
                if (vmask[r]) acc += g_hb[r*HH + mm] * wrow[r];
        }
    }
    part2[pp][i] = acc;
    __syncthreads();

    if (tid < 32){
        float y = bfc[o];
        #pragma unroll
        for (int p2 = 0; p2 < 8; p2++) y += part2[p2][tid];
        float s = y, s2 = y*y;
        #pragma unroll
        for (int off = 16; off; off >>= 1){
            s  += __shfl_xor_sync(0xffffffffu, s,  off);
            s2 += __shfl_xor_sync(0xffffffffu, s2, off);
        }
        float mean = s * (1.f/32.f);
        float var  = s2 * (1.f/32.f) - mean*mean;
        float yn = gamma[o]*(y-mean)*rsqrtf(var + 1e-5f) + beta[o];
        yn = fmaxf(yn, 0.f);
        float mx = yn;
        #pragma unroll
        for (int off = 16; off; off >>= 1) mx = fmaxf(mx, __shfl_xor_sync(0xffffffffu, mx, off));
        float e = __expf(yn - mx), se = e;
        #pragma unroll
        for (int off = 16; off; off >>= 1) se += __shfl_xor_sync(0xffffffffu, se, off);
        out[tid*OO + o] = yn - mx - __logf(se);
    }
}

// ---------------- launcher ----------------
extern "C" void kernel_launch(void* const* d_in, const int* in_sizes, int n_in,
                              void* d_out, int out_size)
{
    const int*  x     = (const int*)d_in[0];
    const void* xmask = d_in[1];
    const float* xfeat = (const float*)d_in[2];
    const int*  lens  = (const int*)d_in[3];

    // clause/cls scalars at 4,5 — self-correct if the harness dropped them
    int base = 6;
    if (n_in < 21 || in_sizes[6] != 50000*512) base = 4;

    const float* emb   = (const float*)d_in[base+0];
    const float* wattn = (const float*)d_in[base+1];
    const float* battn = (const float*)d_in[base+2];
    const float* Wih_f = (const float*)d_in[base+3];
    const float* Whh_f = (const float*)d_in[base+4];
    const float* bih_f = (const float*)d_in[base+5];
    const float* bhh_f = (const float*)d_in[base+6];
    const float* Wih_b = (const float*)d_in[base+7];
    const float* bih_b = (const float*)d_in[base+9];
    const float* bhh_b = (const float*)d_in[base+10];
    const float* Wfc   = (const float*)d_in[base+11];
    const float* bfc   = (const float*)d_in[base+12];
    const float* gamma = (const float*)d_in[base+13];
    const float* beta  = (const float*)d_in[base+14];
    float* out = (float*)d_out;
    (void)in_sizes; (void)out_size;

    init_kernel<<<66,256>>>((const unsigned*)xmask, lens);
    attn_kernel<<<BB*PP,256>>>(x, xmask, xfeat, emb, wattn, battn, lens);
    pregemm_kernel<<<dim3(13,32),256>>>(Wih_f, bih_f, bhh_f, Wih_b, bih_b, bhh_b);
    recur_kernel<<<NBLK_RECUR,256>>>(Whh_f);
    bwd_kernel<<<64,256>>>();
    epi_kernel<<<OO,256>>>(lens, Wfc, bfc, gamma, beta, out);
}